// round 15
// baseline (speedup 1.0000x reference)
#include <cuda_runtime.h>
#include <cstdint>

// ============================================================================
// SpikingReservoirLoaded: B=64, T=500, R=2048, beta=0.9, thr=1.0, zero reset.
//   V_t = beta*V_{t-1} + x[b,t]*w_in[r] + sum_{j: S_{t-1}[b,j]=1} W[j,r]
//
// R13 = R11 (best passing, 10.45ms) with the overflow straggler fixed:
//  * overflow continuation (list entries beyond CAP_B) was a SERIAL
//    LDG->add loop: each iteration exposed ~260cyc L2 latency; batches
//    with n ~ 820 burned ~13k cyc and the chip barrier waited for them.
//    Now: uint4 idx chunks with depth-2 prefetch + same 8xLDS/8xadd body;
//    tail (<8) loads idx upfront then adds in order. Bit-exact (strict
//    ascending j, single f32x2 accumulator unchanged).
//  * CAP_B 768 -> 784 (fewer overflow batches; smem 231744B <= limit).
//  * x[b,t] LDG hoisted above the gather (off the LIF critical path).
// Everything else identical to R11.
// ============================================================================

#define T_STEPS   500
#define BATCH     64
#define RSIZE     2048
#define NWORDS32  64
#define NBLOCKS   128
#define NTHREADS  768
#define TBR       (500LL * 64LL * 2048LL) // 65,536,000

#define CAP_B     784                     // smem idx entries per batch (mult of 8)
#define OVF_CAP   1280                    // global overflow entries (784+1280>2048)
#define SMEM_W_BYTES   ((RSIZE + 1) * 64)             // 131136 (incl. zero row 2048)
#define SMEM_IDX_OFF   (SMEM_W_BYTES)                 // 16B aligned
#define SMEM_CNT_OFF   (SMEM_IDX_OFF + BATCH * CAP_B * 2)   // 231488
#define SMEM_BYTES     (SMEM_CNT_OFF + BATCH * 4)           // 231744

__device__ unsigned g_masks[2][BATCH][NWORDS32];
__device__ unsigned g_flags[NBLOCKS];             // per-CTA barrier flags
__device__ unsigned long long g_spike_count;
__device__ __align__(16) unsigned short g_ovf[NBLOCKS][BATCH][OVF_CAP];

__global__ void snn_init_kernel() {
    int t = threadIdx.x;
    for (int i = t; i < BATCH * NWORDS32; i += blockDim.x)
        (&g_masks[0][0][0])[i] = 0u;               // S0 = 0 (read at step 0)
    if (t < NBLOCKS) g_flags[t] = 0u;
    if (t == 0) g_spike_count = 0ull;
}

__device__ __forceinline__ void st_release_gpu(unsigned* p, unsigned v) {
    asm volatile("st.release.gpu.global.u32 [%0], %1;" :: "l"(p), "r"(v) : "memory");
}
__device__ __forceinline__ unsigned ld_acquire_gpu(const unsigned* p) {
    unsigned v;
    asm volatile("ld.acquire.gpu.global.u32 %0, [%1];" : "=r"(v) : "l"(p) : "memory");
    return v;
}
// packed fp32 pair add: per-lane IEEE rn add, bit-identical to scalar FADDs
__device__ __forceinline__ unsigned long long add_f32x2(unsigned long long a,
                                                        unsigned long long b) {
    unsigned long long r;
    asm("add.rn.f32x2 %0, %1, %2;" : "=l"(r) : "l"(a), "l"(b));
    return r;
}

__global__ void __launch_bounds__(NTHREADS, 1)
snn_kernel(const float* __restrict__ x,      // (B, T)   [B,T,1]
           const float* __restrict__ w_in,   // (R)
           const float* __restrict__ W,      // (R, R) row-major: W[j*R + r]
           float* __restrict__ spike_out,    // (T,B,R) or null (4B-aligned only!)
           float* __restrict__ mem_out,      // (T,B,R) or null (4B-aligned only!)
           float* avg_out)                   // scalar or null
{
    extern __shared__ char smem[];
    float2* Ws2 = reinterpret_cast<float2*>(smem);                 // [2049][8]
    unsigned short* sidx = reinterpret_cast<unsigned short*>(smem + SMEM_IDX_OFF);
    int* scnt = reinterpret_cast<int*>(smem + SMEM_CNT_OFF);

    const int tid  = threadIdx.x;
    const int cta  = blockIdx.x;
    const int lane = tid & 31;
    const int warp = tid >> 5;          // 0..23
    const int b    = tid >> 3;          // batch (valid for tid<512)
    const int p    = tid & 7;           // column pair 0..7
    const int col0 = cta * 16 + p * 2;
    const bool gatherer = (tid < 512);

    // ---- load W column slice into smem + zero dummy row 2048 ----
    for (int idx = tid; idx < (RSIZE + 1) * 8; idx += NTHREADS) {
        int j = idx >> 3, q = idx & 7;
        float2 v = make_float2(0.f, 0.f);
        if (j < RSIZE)
            v = *reinterpret_cast<const float2*>(W + (size_t)j * RSIZE + cta * 16 + q * 2);
        Ws2[j * 8 + q] = v;
    }

    const float2 win2 = *reinterpret_cast<const float2*>(w_in + col0);
    const float* __restrict__ xb = x + (gatherer ? b : 0) * T_STEPS;
    const char* wbase = smem + (p << 3);   // + (j<<6) gives &Ws2[j*8+p]

    float2 V = make_float2(0.f, 0.f);
    unsigned cnt = 0;
    const long long recBase = (long long)(gatherer ? b : 0) * RSIZE + col0;

    // build assignment: warp w -> batches {w, w+24, w+48(if w<16)}
    const int nb = (warp < 16) ? 3 : 2;

    for (int t = 0; t < T_STEPS; ++t) {
        // ================= build index lists (24 warps, 2-3 batches each) ===
        {
            const unsigned* gm = &g_masks[t & 1][0][0];
            #pragma unroll
            for (int q = 0; q < 3; ++q) {
                if (q >= nb) break;
                const int bq = warp + q * 24;
                const unsigned* mb = gm + bq * NWORDS32;
                unsigned w0 = __ldcg(mb + lane);
                unsigned w1 = __ldcg(mb + 32 + lane);
                int base = 0;
                unsigned short* L = sidx + bq * CAP_B;
                unsigned short* G = &g_ovf[cta][bq][0];
                #pragma unroll
                for (int h = 0; h < 2; ++h) {
                    unsigned word = (h == 0) ? w0 : w1;
                    int c = __popc(word);
                    int s = c;                      // inclusive scan of popc
                    #pragma unroll
                    for (int d = 1; d < 32; d <<= 1) {
                        int u = __shfl_up_sync(0xffffffffu, s, d);
                        if (lane >= d) s += u;
                    }
                    int pos = base + s - c;
                    int jb = (h * 32 + lane) * 32;
                    unsigned m = word;
                    while (m) {
                        int bit = __ffs(m) - 1;
                        m &= m - 1;
                        unsigned short jv = (unsigned short)(jb + bit);
                        if (pos < CAP_B) L[pos] = jv;
                        else             G[pos - CAP_B] = jv;
                        ++pos;
                    }
                    base += __shfl_sync(0xffffffffu, s, 31);
                }
                // pad list to multiple of 8 with dummy row 2048 (adds +0.0)
                if (base < CAP_B) {
                    int padTo = (base + 7) & ~7;
                    if (padTo > CAP_B) padTo = CAP_B;
                    if (lane < padTo - base) L[base + lane] = (unsigned short)RSIZE;
                }
                if (lane == 0) scnt[bq] = base;
            }
        }
        __syncthreads();   // lists + g_ovf visible CTA-wide

        bool s0 = false, s1 = false;
        if (gatherer) {
            float xv = __ldg(xb + t);        // hoisted: off the LIF critical path

            // ============== gather: ascending j, packed accumulator =========
            unsigned long long acc = 0ull;   // (ax, ay) as f32x2
            int n  = scnt[b];
            {
                int ns = (n < CAP_B) ? ((n + 7) & ~7) : CAP_B;   // padded length
                const uint4* L4 = reinterpret_cast<const uint4*>(sidx + b * CAP_B);
                int trips = ns >> 3;
                if (trips > 0) {
                    uint4 v = L4[0];
                    #pragma unroll 1
                    for (int i = 0; i < trips; ++i) {
                        int nx = i + 1 < trips ? i + 1 : i;
                        uint4 vn = L4[nx];                      // prefetch
                        unsigned o0 = (v.x & 0xffffu) << 6, o1 = (v.x >> 16) << 6;
                        unsigned o2 = (v.y & 0xffffu) << 6, o3 = (v.y >> 16) << 6;
                        unsigned o4 = (v.z & 0xffffu) << 6, o5 = (v.z >> 16) << 6;
                        unsigned o6 = (v.w & 0xffffu) << 6, o7 = (v.w >> 16) << 6;
                        unsigned long long r0 = *reinterpret_cast<const unsigned long long*>(wbase + o0);
                        unsigned long long r1 = *reinterpret_cast<const unsigned long long*>(wbase + o1);
                        unsigned long long r2 = *reinterpret_cast<const unsigned long long*>(wbase + o2);
                        unsigned long long r3 = *reinterpret_cast<const unsigned long long*>(wbase + o3);
                        unsigned long long r4 = *reinterpret_cast<const unsigned long long*>(wbase + o4);
                        unsigned long long r5 = *reinterpret_cast<const unsigned long long*>(wbase + o5);
                        unsigned long long r6 = *reinterpret_cast<const unsigned long long*>(wbase + o6);
                        unsigned long long r7 = *reinterpret_cast<const unsigned long long*>(wbase + o7);
                        acc = add_f32x2(acc, r0);
                        acc = add_f32x2(acc, r1);
                        acc = add_f32x2(acc, r2);
                        acc = add_f32x2(acc, r3);
                        acc = add_f32x2(acc, r4);
                        acc = add_f32x2(acc, r5);
                        acc = add_f32x2(acc, r6);
                        acc = add_f32x2(acc, r7);
                        v = vn;
                    }
                }
            }
            if (n > CAP_B) {   // overflow continuation, PIPELINED (ascending)
                const unsigned short* G = &g_ovf[cta][b][0];
                int no = n - CAP_B;
                int chunks = no >> 3;
                if (chunks > 0) {
                    const uint4* G4 = reinterpret_cast<const uint4*>(G);
                    uint4 c0 = __ldg(G4);
                    uint4 c1 = (chunks > 1) ? __ldg(G4 + 1) : c0;
                    #pragma unroll 1
                    for (int i = 0; i < chunks; ++i) {
                        uint4 cn = (i + 2 < chunks) ? __ldg(G4 + i + 2) : c1;
                        unsigned o0 = (c0.x & 0xffffu) << 6, o1 = (c0.x >> 16) << 6;
                        unsigned o2 = (c0.y & 0xffffu) << 6, o3 = (c0.y >> 16) << 6;
                        unsigned o4 = (c0.z & 0xffffu) << 6, o5 = (c0.z >> 16) << 6;
                        unsigned o6 = (c0.w & 0xffffu) << 6, o7 = (c0.w >> 16) << 6;
                        unsigned long long r0 = *reinterpret_cast<const unsigned long long*>(wbase + o0);
                        unsigned long long r1 = *reinterpret_cast<const unsigned long long*>(wbase + o1);
                        unsigned long long r2 = *reinterpret_cast<const unsigned long long*>(wbase + o2);
                        unsigned long long r3 = *reinterpret_cast<const unsigned long long*>(wbase + o3);
                        unsigned long long r4 = *reinterpret_cast<const unsigned long long*>(wbase + o4);
                        unsigned long long r5 = *reinterpret_cast<const unsigned long long*>(wbase + o5);
                        unsigned long long r6 = *reinterpret_cast<const unsigned long long*>(wbase + o6);
                        unsigned long long r7 = *reinterpret_cast<const unsigned long long*>(wbase + o7);
                        acc = add_f32x2(acc, r0);
                        acc = add_f32x2(acc, r1);
                        acc = add_f32x2(acc, r2);
                        acc = add_f32x2(acc, r3);
                        acc = add_f32x2(acc, r4);
                        acc = add_f32x2(acc, r5);
                        acc = add_f32x2(acc, r6);
                        acc = add_f32x2(acc, r7);
                        c0 = c1; c1 = cn;
                    }
                }
                int rem = no & 7;
                if (rem) {
                    const unsigned short* Gt = G + (chunks << 3);
                    unsigned short tj[7];
                    #pragma unroll
                    for (int k2 = 0; k2 < 7; ++k2)       // idx upfront, independent
                        if (k2 < rem) tj[k2] = __ldg(Gt + k2);
                    #pragma unroll
                    for (int k2 = 0; k2 < 7; ++k2)       // adds in ascending order
                        if (k2 < rem)
                            acc = add_f32x2(acc,
                                *reinterpret_cast<const unsigned long long*>(
                                    wbase + ((unsigned)tj[k2] << 6)));
                }
            }
            float ax = __uint_as_float((unsigned)(acc & 0xffffffffull));
            float ay = __uint_as_float((unsigned)(acc >> 32));

            // ---- LIF update (identical arithmetic to verified R11) ----
            float v0 = fmaf(0.9f, V.x, xv * win2.x) + ax;
            float v1 = fmaf(0.9f, V.y, xv * win2.y) + ay;
            s0 = (v0 >= 1.0f);
            s1 = (v1 >= 1.0f);
            V.x = s0 ? 0.f : v0;
            V.y = s1 ? 0.f : v1;
            cnt += (unsigned)s0 + (unsigned)s1;

            // ---- publish 16-bit spike slice for (b, cta) ----
            unsigned hv = ((unsigned)s0 | ((unsigned)s1 << 1)) << (p * 2);
            hv |= __shfl_xor_sync(0xffffffffu, hv, 1);
            hv |= __shfl_xor_sync(0xffffffffu, hv, 2);
            hv |= __shfl_xor_sync(0xffffffffu, hv, 4);
            if (p == 0) {
                unsigned short* m16 =
                    reinterpret_cast<unsigned short*>(&g_masks[(t + 1) & 1][0][0]);
                m16[b * 128 + cta] = (unsigned short)hv;
            }
        }

        // ---- chip barrier: parallel flag array ----
        __syncthreads();                         // CTA's mask stores done
        if (tid == 0) st_release_gpu(&g_flags[cta], (unsigned)(t + 1));
        // records off the critical path (overlap with barrier wait)
        if (gatherer && spike_out) {
            long long off = (long long)t * (BATCH * RSIZE) + recBase;
            spike_out[off]     = s0 ? 1.f : 0.f;
            spike_out[off + 1] = s1 ? 1.f : 0.f;
            mem_out[off]     = V.x;
            mem_out[off + 1] = V.y;
        }
        if (tid < NBLOCKS) {
            while (ld_acquire_gpu(&g_flags[tid]) < (unsigned)(t + 1)) { }
        }
        __syncthreads();
    }

    // ---- global spike count -> average firing rate ----
    #pragma unroll
    for (int s = 16; s; s >>= 1)
        cnt += __shfl_down_sync(0xffffffffu, cnt, s);
    if (lane == 0 && cnt) atomicAdd(&g_spike_count, (unsigned long long)cnt);

    __syncthreads();
    if (tid == 0) st_release_gpu(&g_flags[cta], (unsigned)(T_STEPS + 1));

    if (cta == 0) {
        if (tid < NBLOCKS) {
            while (ld_acquire_gpu(&g_flags[tid]) < (unsigned)(T_STEPS + 1)) { }
        }
        __syncthreads();
        if (tid == 0 && avg_out) {
            double c = (double)g_spike_count;
            *avg_out = (float)(c / (double)TBR);
        }
    }
}

extern "C" void kernel_launch(void* const* d_in, const int* in_sizes, int n_in,
                              void* d_out, int out_size) {
    (void)in_sizes; (void)n_in;
    const float* x    = (const float*)d_in[0];   // (64, 500, 1)
    const float* w_in = (const float*)d_in[1];   // (2048, 1)
    const float* W    = (const float*)d_in[2];   // (2048, 2048)
    float* out = (float*)d_out;

    float* spike = nullptr;
    float* mem   = nullptr;
    float* avg   = nullptr;
    const long long tbr = TBR;
    const long long osz = (long long)out_size;

    if (osz == 2 * tbr + 1) {            // [avg, spikes, mem]
        avg = out; spike = out + 1; mem = out + 1 + tbr;
    } else if (osz == 2 * tbr) {         // [spikes, mem]
        spike = out; mem = out + tbr;
    } else if (osz == 1) {               // scalar only
        avg = out;
    } else if (osz > 2 * tbr + 1) {      // unknown but big enough: assume concat
        avg = out; spike = out + 1; mem = out + 1 + tbr;
    } else {
        avg = out;
    }

    static int smem_set = 0;
    if (!smem_set) {
        cudaFuncSetAttribute(snn_kernel,
                             cudaFuncAttributeMaxDynamicSharedMemorySize, SMEM_BYTES);
        smem_set = 1;
    }

    snn_init_kernel<<<1, 256>>>();
    snn_kernel<<<NBLOCKS, NTHREADS, SMEM_BYTES>>>(x, w_in, W, spike, mem, avg);
}

// round 16
// speedup vs baseline: 1.3269x; 1.3269x over previous
#include <cuda_runtime.h>
#include <cstdint>

// ============================================================================
// SpikingReservoirLoaded: B=64, T=500, R=2048, beta=0.9, thr=1.0, zero reset.
//   V_t = beta*V_{t-1} + x[b,t]*w_in[r] + sum_{j: S_{t-1}[b,j]=1} W[j,r]
//
// R15 = R11 (best passing, 10.45ms) with ONE change: the gather uses
// 4 threads per batch, each owning 4 columns via LDS.128 (ulonglong2) and
// two add.rn.f32x2, instead of 8 threads x LDS.64. Per (row,col) issue cost
// drops 2.0 -> 1.25 inst; gather thread count halves (256). Per-column fp
// sequence unchanged (strict ascending j, one accumulator lane) -> bit-exact.
// R13's regressing changes (overflow __ldg pipeline, CAP_B=784) are fully
// reverted: overflow path is R11's plain-load serial loop, CAP_B=768.
// ============================================================================

#define T_STEPS   500
#define BATCH     64
#define RSIZE     2048
#define NWORDS32  64
#define NBLOCKS   128
#define NTHREADS  768
#define GATHER_T  256                     // 64 batches x 4 col-quad threads
#define TBR       (500LL * 64LL * 2048LL) // 65,536,000

#define CAP_B     768                     // smem idx entries per batch (mult of 8)
#define OVF_CAP   1280                    // global overflow entries
#define SMEM_W_BYTES   ((RSIZE + 1) * 64)             // 131136 (incl. zero row 2048)
#define SMEM_IDX_OFF   (SMEM_W_BYTES)                 // 16B aligned
#define SMEM_CNT_OFF   (SMEM_IDX_OFF + BATCH * CAP_B * 2)   // 229440
#define SMEM_BYTES     (SMEM_CNT_OFF + BATCH * 4)           // 229696

__device__ unsigned g_masks[2][BATCH][NWORDS32];
__device__ unsigned g_flags[NBLOCKS];             // per-CTA barrier flags
__device__ unsigned long long g_spike_count;
__device__ __align__(16) unsigned short g_ovf[NBLOCKS][BATCH][OVF_CAP];

__global__ void snn_init_kernel() {
    int t = threadIdx.x;
    for (int i = t; i < BATCH * NWORDS32; i += blockDim.x)
        (&g_masks[0][0][0])[i] = 0u;               // S0 = 0 (read at step 0)
    if (t < NBLOCKS) g_flags[t] = 0u;
    if (t == 0) g_spike_count = 0ull;
}

__device__ __forceinline__ void st_release_gpu(unsigned* p, unsigned v) {
    asm volatile("st.release.gpu.global.u32 [%0], %1;" :: "l"(p), "r"(v) : "memory");
}
__device__ __forceinline__ unsigned ld_acquire_gpu(const unsigned* p) {
    unsigned v;
    asm volatile("ld.acquire.gpu.global.u32 %0, [%1];" : "=r"(v) : "l"(p) : "memory");
    return v;
}
// packed fp32 pair add: per-lane IEEE rn add, bit-identical to scalar FADDs
__device__ __forceinline__ unsigned long long add_f32x2(unsigned long long a,
                                                        unsigned long long b) {
    unsigned long long r;
    asm("add.rn.f32x2 %0, %1, %2;" : "=l"(r) : "l"(a), "l"(b));
    return r;
}

__global__ void __launch_bounds__(NTHREADS, 1)
snn_kernel(const float* __restrict__ x,      // (B, T)   [B,T,1]
           const float* __restrict__ w_in,   // (R)
           const float* __restrict__ W,      // (R, R) row-major: W[j*R + r]
           float* __restrict__ spike_out,    // (T,B,R) or null (4B-aligned only!)
           float* __restrict__ mem_out,      // (T,B,R) or null (4B-aligned only!)
           float* avg_out)                   // scalar or null
{
    extern __shared__ char smem[];
    float2* Ws2 = reinterpret_cast<float2*>(smem);                 // [2049][8]
    unsigned short* sidx = reinterpret_cast<unsigned short*>(smem + SMEM_IDX_OFF);
    int* scnt = reinterpret_cast<int*>(smem + SMEM_CNT_OFF);

    const int tid  = threadIdx.x;
    const int cta  = blockIdx.x;
    const int lane = tid & 31;
    const int warp = tid >> 5;          // 0..23
    const bool gatherer = (tid < GATHER_T);
    const int b    = gatherer ? (tid >> 2) : 0;   // batch 0..63
    const int q    = tid & 3;                      // column quad 0..3
    const int col0 = cta * 16 + q * 4;

    // ---- load W column slice into smem + zero dummy row 2048 ----
    for (int idx = tid; idx < (RSIZE + 1) * 8; idx += NTHREADS) {
        int j = idx >> 3, qq = idx & 7;
        float2 v = make_float2(0.f, 0.f);
        if (j < RSIZE)
            v = *reinterpret_cast<const float2*>(W + (size_t)j * RSIZE + cta * 16 + qq * 2);
        Ws2[j * 8 + qq] = v;
    }

    const float4 win4 = *reinterpret_cast<const float4*>(w_in + col0);
    const float* __restrict__ xb = x + b * T_STEPS;
    const char* wbase = smem + (q << 4);   // + (j<<6) gives &Ws2[j*8 + q*2] (16B)

    float4 V = make_float4(0.f, 0.f, 0.f, 0.f);
    unsigned cnt = 0;
    const long long recBase = (long long)b * RSIZE + col0;

    // build assignment: warp w -> batches {w, w+24, w+48(if w<16)}
    const int nb = (warp < 16) ? 3 : 2;

    for (int t = 0; t < T_STEPS; ++t) {
        // ================= build index lists (24 warps, 2-3 batches each) ===
        {
            const unsigned* gm = &g_masks[t & 1][0][0];
            #pragma unroll
            for (int qq = 0; qq < 3; ++qq) {
                if (qq >= nb) break;
                const int bq = warp + qq * 24;
                const unsigned* mb = gm + bq * NWORDS32;
                unsigned w0 = __ldcg(mb + lane);
                unsigned w1 = __ldcg(mb + 32 + lane);
                int base = 0;
                unsigned short* L = sidx + bq * CAP_B;
                unsigned short* G = &g_ovf[cta][bq][0];
                #pragma unroll
                for (int h = 0; h < 2; ++h) {
                    unsigned word = (h == 0) ? w0 : w1;
                    int c = __popc(word);
                    int s = c;                      // inclusive scan of popc
                    #pragma unroll
                    for (int d = 1; d < 32; d <<= 1) {
                        int u = __shfl_up_sync(0xffffffffu, s, d);
                        if (lane >= d) s += u;
                    }
                    int pos = base + s - c;
                    int jb = (h * 32 + lane) * 32;
                    unsigned m = word;
                    while (m) {
                        int bit = __ffs(m) - 1;
                        m &= m - 1;
                        unsigned short jv = (unsigned short)(jb + bit);
                        if (pos < CAP_B) L[pos] = jv;
                        else             G[pos - CAP_B] = jv;
                        ++pos;
                    }
                    base += __shfl_sync(0xffffffffu, s, 31);
                }
                // pad list to multiple of 8 with dummy row 2048 (adds +0.0)
                if (base < CAP_B) {
                    int padTo = (base + 7) & ~7;
                    if (padTo > CAP_B) padTo = CAP_B;
                    if (lane < padTo - base) L[base + lane] = (unsigned short)RSIZE;
                }
                if (lane == 0) scnt[bq] = base;
            }
        }
        __syncthreads();   // lists + g_ovf visible CTA-wide

        bool s0 = false, s1 = false, s2 = false, s3 = false;
        if (gatherer) {
            float xv = __ldg(xb + t);

            // ====== gather: ascending j, two packed accumulators (4 cols) ===
            unsigned long long acc01 = 0ull;   // cols (col0, col0+1)
            unsigned long long acc23 = 0ull;   // cols (col0+2, col0+3)
            int n = scnt[b];
            {
                int ns = (n < CAP_B) ? ((n + 7) & ~7) : CAP_B;   // padded length
                const uint4* L4 = reinterpret_cast<const uint4*>(sidx + b * CAP_B);
                int trips = ns >> 3;
                if (trips > 0) {
                    uint4 v = L4[0];
                    #pragma unroll 1
                    for (int i = 0; i < trips; ++i) {
                        int nx = i + 1 < trips ? i + 1 : i;
                        uint4 vn = L4[nx];                      // prefetch
                        unsigned o0 = (v.x & 0xffffu) << 6, o1 = (v.x >> 16) << 6;
                        unsigned o2 = (v.y & 0xffffu) << 6, o3 = (v.y >> 16) << 6;
                        unsigned o4 = (v.z & 0xffffu) << 6, o5 = (v.z >> 16) << 6;
                        unsigned o6 = (v.w & 0xffffu) << 6, o7 = (v.w >> 16) << 6;
                        ulonglong2 r0 = *reinterpret_cast<const ulonglong2*>(wbase + o0);
                        ulonglong2 r1 = *reinterpret_cast<const ulonglong2*>(wbase + o1);
                        ulonglong2 r2 = *reinterpret_cast<const ulonglong2*>(wbase + o2);
                        ulonglong2 r3 = *reinterpret_cast<const ulonglong2*>(wbase + o3);
                        ulonglong2 r4 = *reinterpret_cast<const ulonglong2*>(wbase + o4);
                        ulonglong2 r5 = *reinterpret_cast<const ulonglong2*>(wbase + o5);
                        ulonglong2 r6 = *reinterpret_cast<const ulonglong2*>(wbase + o6);
                        ulonglong2 r7 = *reinterpret_cast<const ulonglong2*>(wbase + o7);
                        acc01 = add_f32x2(acc01, r0.x); acc23 = add_f32x2(acc23, r0.y);
                        acc01 = add_f32x2(acc01, r1.x); acc23 = add_f32x2(acc23, r1.y);
                        acc01 = add_f32x2(acc01, r2.x); acc23 = add_f32x2(acc23, r2.y);
                        acc01 = add_f32x2(acc01, r3.x); acc23 = add_f32x2(acc23, r3.y);
                        acc01 = add_f32x2(acc01, r4.x); acc23 = add_f32x2(acc23, r4.y);
                        acc01 = add_f32x2(acc01, r5.x); acc23 = add_f32x2(acc23, r5.y);
                        acc01 = add_f32x2(acc01, r6.x); acc23 = add_f32x2(acc23, r6.y);
                        acc01 = add_f32x2(acc01, r7.x); acc23 = add_f32x2(acc23, r7.y);
                        v = vn;
                    }
                }
                if (n > CAP_B) {   // overflow continuation (R11-style, plain loads)
                    const unsigned short* G = &g_ovf[cta][b][0];
                    int no = n - CAP_B;
                    #pragma unroll 1
                    for (int k2 = 0; k2 < no; ++k2) {
                        ulonglong2 r = *reinterpret_cast<const ulonglong2*>(
                            wbase + ((unsigned)G[k2] << 6));
                        acc01 = add_f32x2(acc01, r.x);
                        acc23 = add_f32x2(acc23, r.y);
                    }
                }
            }
            float a0 = __uint_as_float((unsigned)(acc01 & 0xffffffffull));
            float a1 = __uint_as_float((unsigned)(acc01 >> 32));
            float a2 = __uint_as_float((unsigned)(acc23 & 0xffffffffull));
            float a3 = __uint_as_float((unsigned)(acc23 >> 32));

            // ---- LIF update (identical per-column arithmetic) ----
            float v0 = fmaf(0.9f, V.x, xv * win4.x) + a0;
            float v1 = fmaf(0.9f, V.y, xv * win4.y) + a1;
            float v2 = fmaf(0.9f, V.z, xv * win4.z) + a2;
            float v3 = fmaf(0.9f, V.w, xv * win4.w) + a3;
            s0 = (v0 >= 1.0f); s1 = (v1 >= 1.0f);
            s2 = (v2 >= 1.0f); s3 = (v3 >= 1.0f);
            V.x = s0 ? 0.f : v0;
            V.y = s1 ? 0.f : v1;
            V.z = s2 ? 0.f : v2;
            V.w = s3 ? 0.f : v3;
            cnt += (unsigned)s0 + (unsigned)s1 + (unsigned)s2 + (unsigned)s3;

            // ---- publish 16-bit spike slice for (b, cta) ----
            unsigned hv = ((unsigned)s0 | ((unsigned)s1 << 1) |
                           ((unsigned)s2 << 2) | ((unsigned)s3 << 3)) << (q * 4);
            hv |= __shfl_xor_sync(0xffffffffu, hv, 1);
            hv |= __shfl_xor_sync(0xffffffffu, hv, 2);
            if (q == 0) {
                unsigned short* m16 =
                    reinterpret_cast<unsigned short*>(&g_masks[(t + 1) & 1][0][0]);
                m16[b * 128 + cta] = (unsigned short)hv;
            }
        }

        // ---- chip barrier: parallel flag array ----
        __syncthreads();                         // CTA's mask stores done
        if (tid == 0) st_release_gpu(&g_flags[cta], (unsigned)(t + 1));
        // records off the critical path (overlap with barrier wait)
        if (gatherer && spike_out) {
            long long off = (long long)t * (BATCH * RSIZE) + recBase;
            spike_out[off]     = s0 ? 1.f : 0.f;
            spike_out[off + 1] = s1 ? 1.f : 0.f;
            spike_out[off + 2] = s2 ? 1.f : 0.f;
            spike_out[off + 3] = s3 ? 1.f : 0.f;
            mem_out[off]     = V.x;
            mem_out[off + 1] = V.y;
            mem_out[off + 2] = V.z;
            mem_out[off + 3] = V.w;
        }
        if (tid < NBLOCKS) {
            while (ld_acquire_gpu(&g_flags[tid]) < (unsigned)(t + 1)) { }
        }
        __syncthreads();
    }

    // ---- global spike count -> average firing rate ----
    #pragma unroll
    for (int s = 16; s; s >>= 1)
        cnt += __shfl_down_sync(0xffffffffu, cnt, s);
    if (lane == 0 && cnt) atomicAdd(&g_spike_count, (unsigned long long)cnt);

    __syncthreads();
    if (tid == 0) st_release_gpu(&g_flags[cta], (unsigned)(T_STEPS + 1));

    if (cta == 0) {
        if (tid < NBLOCKS) {
            while (ld_acquire_gpu(&g_flags[tid]) < (unsigned)(T_STEPS + 1)) { }
        }
        __syncthreads();
        if (tid == 0 && avg_out) {
            double c = (double)g_spike_count;
            *avg_out = (float)(c / (double)TBR);
        }
    }
}

extern "C" void kernel_launch(void* const* d_in, const int* in_sizes, int n_in,
                              void* d_out, int out_size) {
    (void)in_sizes; (void)n_in;
    const float* x    = (const float*)d_in[0];   // (64, 500, 1)
    const float* w_in = (const float*)d_in[1];   // (2048, 1)
    const float* W    = (const float*)d_in[2];   // (2048, 2048)
    float* out = (float*)d_out;

    float* spike = nullptr;
    float* mem   = nullptr;
    float* avg   = nullptr;
    const long long tbr = TBR;
    const long long osz = (long long)out_size;

    if (osz == 2 * tbr + 1) {            // [avg, spikes, mem]
        avg = out; spike = out + 1; mem = out + 1 + tbr;
    } else if (osz == 2 * tbr) {         // [spikes, mem]
        spike = out; mem = out + tbr;
    } else if (osz == 1) {               // scalar only
        avg = out;
    } else if (osz > 2 * tbr + 1) {      // unknown but big enough: assume concat
        avg = out; spike = out + 1; mem = out + 1 + tbr;
    } else {
        avg = out;
    }

    static int smem_set = 0;
    if (!smem_set) {
        cudaFuncSetAttribute(snn_kernel,
                             cudaFuncAttributeMaxDynamicSharedMemorySize, SMEM_BYTES);
        smem_set = 1;
    }

    snn_init_kernel<<<1, 256>>>();
    snn_kernel<<<NBLOCKS, NTHREADS, SMEM_BYTES>>>(x, w_in, W, spike, mem, avg);
}